// round 1
// baseline (speedup 1.0000x reference)
#include <cuda_runtime.h>
#include <math.h>

#define N_NODES 50000
#define N_EDGES 800000
#define IN_DIM  256
#define C1      128     // HEADS * 32
#define HEADS   4
#define HID1    32
#define OUT_DIM 64

// ---------------- scratch (device globals; no allocation allowed) ------------
__device__ __align__(16) float g_z1 [N_NODES * C1];
__device__ __align__(16) float g_es1[N_NODES * HEADS];
__device__ __align__(16) float g_ed1[N_NODES * HEADS];
__device__ __align__(16) float g_h1 [N_NODES * C1];
__device__ __align__(16) float g_z2 [N_NODES * OUT_DIM];
__device__ float g_es2[N_NODES];
__device__ float g_ed2[N_NODES];
__device__ int   g_deg[N_NODES];
__device__ int   g_pos[N_NODES];
__device__ int   g_off[N_NODES + 1];
__device__ int   g_ssrc[N_EDGES];

__device__ __forceinline__ float leaky(float x) { return x > 0.f ? x : 0.01f * x; }
__device__ __forceinline__ float elu_f(float x) { return x > 0.f ? x : (__expf(x) - 1.f); }

// ---------------- CSR build --------------------------------------------------
__global__ void k_zero() {
    int i = blockIdx.x * blockDim.x + threadIdx.x;
    if (i < N_NODES) { g_deg[i] = 0; g_pos[i] = 0; }
}

__global__ void k_hist(const int* __restrict__ dst) {
    int e = blockIdx.x * blockDim.x + threadIdx.x;
    if (e < N_EDGES) atomicAdd(&g_deg[dst[e]], 1);
}

__global__ void k_scan() {
    __shared__ int sm[1024];
    int tid = threadIdx.x;
    const int CH = (N_NODES + 1023) / 1024;   // 49
    int base = tid * CH;
    int s = 0;
    for (int i = 0; i < CH; i++) {
        int idx = base + i;
        if (idx < N_NODES) s += g_deg[idx];
    }
    sm[tid] = s;
    __syncthreads();
    for (int d = 1; d < 1024; d <<= 1) {
        int v = (tid >= d) ? sm[tid - d] : 0;
        __syncthreads();
        sm[tid] += v;
        __syncthreads();
    }
    int run = sm[tid] - s;   // exclusive prefix
    for (int i = 0; i < CH; i++) {
        int idx = base + i;
        if (idx < N_NODES) { g_off[idx] = run; run += g_deg[idx]; }
    }
    if (tid == 1023) g_off[N_NODES] = sm[1023];
}

__global__ void k_scatter(const int* __restrict__ src, const int* __restrict__ dst) {
    int e = blockIdx.x * blockDim.x + threadIdx.x;
    if (e < N_EDGES) {
        int d = dst[e];
        int p = g_off[d] + atomicAdd(&g_pos[d], 1);
        g_ssrc[p] = src[e];
    }
}

// ---------------- layer-1 GEMM: z1 = h @ W1 (256 -> 128) ---------------------
// smem: sW[256][128] (transposed from [h][k][d]) = 128KB, sx[64][256] = 64KB
__global__ void k_gemm1(const float* __restrict__ x, const float* __restrict__ W1) {
    extern __shared__ float sm[];
    float* sW = sm;                 // 32768 floats
    float* sx = sm + 256 * 128;     // 16384 floats
    int tid = threadIdx.x;          // 512 threads

    for (int i = tid; i < HEADS * IN_DIM * HID1; i += 512) {
        int hh = i >> 13;                 // head
        int k  = (i >> 5) & 255;          // input dim
        int d  = i & 31;                  // hidden dim
        sW[k * 128 + hh * 32 + d] = W1[i];
    }
    __syncthreads();

    int c  = tid & 127;     // output column
    int ng = tid >> 7;      // node group 0..3 (16 nodes each)
    int ntiles = (N_NODES + 63) >> 6;

    for (int tile = blockIdx.x; tile < ntiles; tile += gridDim.x) {
        int n0 = tile << 6;
        __syncthreads();
        for (int i = tid; i < 64 * 256; i += 512) {
            int n = n0 + (i >> 8);
            sx[i] = (n < N_NODES) ? x[n * 256 + (i & 255)] : 0.f;
        }
        __syncthreads();

        float acc[16];
        #pragma unroll
        for (int j = 0; j < 16; j++) acc[j] = 0.f;

        const float* xs = sx + (ng * 16) * 256;
        #pragma unroll 4
        for (int k = 0; k < 256; k++) {
            float wv = sW[k * 128 + c];
            #pragma unroll
            for (int j = 0; j < 16; j++) acc[j] += xs[j * 256 + k] * wv;
        }

        #pragma unroll
        for (int j = 0; j < 16; j++) {
            int n = n0 + ng * 16 + j;
            if (n < N_NODES) g_z1[n * 128 + c] = acc[j];
        }
    }
}

// ---------------- layer-1 attention coefficients -----------------------------
__global__ void k_att1(const float* __restrict__ a1) {
    int gw = (blockIdx.x * blockDim.x + threadIdx.x) >> 5;
    if (gw >= N_NODES) return;
    int lane = threadIdx.x & 31;
    int n = gw;
    const float4 z = *(const float4*)&g_z1[n * 128 + 4 * lane];
    int h  = lane >> 3;
    int d0 = (lane & 7) * 4;
    const float* ap = a1 + h * 64;
    float4 as = *(const float4*)&ap[d0];
    float4 ad = *(const float4*)&ap[32 + d0];
    float es = z.x * as.x + z.y * as.y + z.z * as.z + z.w * as.w;
    float ed = z.x * ad.x + z.y * ad.y + z.z * ad.z + z.w * ad.w;
    #pragma unroll
    for (int o = 4; o; o >>= 1) {
        es += __shfl_xor_sync(0xffffffffu, es, o);
        ed += __shfl_xor_sync(0xffffffffu, ed, o);
    }
    if ((lane & 7) == 0) {
        g_es1[n * 4 + h] = es;
        g_ed1[n * 4 + h] = ed;
    }
}

// ---------------- layer-1 aggregation (warp per node) + ELU ------------------
__global__ void k_agg1() {
    __shared__ float s_ex[8][128];
    int gw = (blockIdx.x * blockDim.x + threadIdx.x) >> 5;
    int lane = threadIdx.x & 31;
    int w = threadIdx.x >> 5;
    if (gw >= N_NODES) return;
    int n = gw;
    int off = g_off[n];
    int deg = g_off[n + 1] - off;

    const float4 ed4 = *(const float4*)&g_ed1[n * 4];

    // pass 1: per-head max (lane-parallel over edges)
    float4 m4 = make_float4(-1e30f, -1e30f, -1e30f, -1e30f);
    for (int i = off + lane; i < off + deg; i += 32) {
        int s = g_ssrc[i];
        float4 es4 = *(const float4*)&g_es1[s * 4];
        m4.x = fmaxf(m4.x, leaky(es4.x + ed4.x));
        m4.y = fmaxf(m4.y, leaky(es4.y + ed4.y));
        m4.z = fmaxf(m4.z, leaky(es4.z + ed4.z));
        m4.w = fmaxf(m4.w, leaky(es4.w + ed4.w));
    }
    #pragma unroll
    for (int o = 16; o; o >>= 1) {
        m4.x = fmaxf(m4.x, __shfl_xor_sync(0xffffffffu, m4.x, o));
        m4.y = fmaxf(m4.y, __shfl_xor_sync(0xffffffffu, m4.y, o));
        m4.z = fmaxf(m4.z, __shfl_xor_sync(0xffffffffu, m4.z, o));
        m4.w = fmaxf(m4.w, __shfl_xor_sync(0xffffffffu, m4.w, o));
    }

    // pass 2: fused softmax + weighted aggregation
    float4 acc = make_float4(0.f, 0.f, 0.f, 0.f);
    float dsum = 0.f;
    int hl = lane >> 3;
    for (int i = off; i < off + deg; i += 32) {
        int nb = off + deg - i; if (nb > 32) nb = 32;
        int s_l = 0;
        float4 ex4 = make_float4(0.f, 0.f, 0.f, 0.f);
        if (lane < nb) {
            s_l = g_ssrc[i + lane];
            float4 es4 = *(const float4*)&g_es1[s_l * 4];
            ex4.x = __expf(leaky(es4.x + ed4.x) - m4.x);
            ex4.y = __expf(leaky(es4.y + ed4.y) - m4.y);
            ex4.z = __expf(leaky(es4.z + ed4.z) - m4.z);
            ex4.w = __expf(leaky(es4.w + ed4.w) - m4.w);
        }
        *(float4*)&s_ex[w][lane * 4] = ex4;
        __syncwarp();
        #pragma unroll 4
        for (int t = 0; t < nb; t++) {
            int s = __shfl_sync(0xffffffffu, s_l, t);
            float ex = s_ex[w][t * 4 + hl];
            const float4 z = *(const float4*)&g_z1[s * 128 + 4 * lane];
            dsum += ex;
            acc.x += ex * z.x;
            acc.y += ex * z.y;
            acc.z += ex * z.z;
            acc.w += ex * z.w;
        }
        __syncwarp();
    }
    float inv = (deg > 0) ? (1.0f / dsum) : 0.f;
    float4 o;
    o.x = elu_f(acc.x * inv);
    o.y = elu_f(acc.y * inv);
    o.z = elu_f(acc.z * inv);
    o.w = elu_f(acc.w * inv);
    *(float4*)&g_h1[n * 128 + 4 * lane] = o;
}

// ---------------- layer-2 GEMM: z2 = h1 @ W2 (128 -> 64) ---------------------
// smem: sW[128][64] = 32KB, sx[128][128] = 64KB
__global__ void k_gemm2(const float* __restrict__ W2) {
    extern __shared__ float sm[];
    float* sW = sm;               // 8192 floats
    float* sx = sm + 128 * 64;    // 16384 floats
    int tid = threadIdx.x;        // 512 threads

    for (int i = tid; i < 128 * 64; i += 512) sW[i] = W2[i];
    __syncthreads();

    int c  = tid & 63;
    int ng = tid >> 6;            // 0..7, 16 nodes each
    int ntiles = (N_NODES + 127) >> 7;

    for (int tile = blockIdx.x; tile < ntiles; tile += gridDim.x) {
        int n0 = tile << 7;
        __syncthreads();
        for (int i = tid; i < 128 * 128; i += 512) {
            int n = n0 + (i >> 7);
            sx[i] = (n < N_NODES) ? g_h1[n * 128 + (i & 127)] : 0.f;
        }
        __syncthreads();

        float acc[16];
        #pragma unroll
        for (int j = 0; j < 16; j++) acc[j] = 0.f;

        const float* xs = sx + (ng * 16) * 128;
        #pragma unroll 4
        for (int k = 0; k < 128; k++) {
            float wv = sW[k * 64 + c];
            #pragma unroll
            for (int j = 0; j < 16; j++) acc[j] += xs[j * 128 + k] * wv;
        }

        #pragma unroll
        for (int j = 0; j < 16; j++) {
            int n = n0 + ng * 16 + j;
            if (n < N_NODES) g_z2[n * 64 + c] = acc[j];
        }
    }
}

// ---------------- layer-2 attention coefficients -----------------------------
__global__ void k_att2(const float* __restrict__ a2) {
    int gw = (blockIdx.x * blockDim.x + threadIdx.x) >> 5;
    if (gw >= N_NODES) return;
    int lane = threadIdx.x & 31;
    int n = gw;
    const float2 z = *(const float2*)&g_z2[n * 64 + 2 * lane];
    float2 as = *(const float2*)&a2[2 * lane];
    float2 ad = *(const float2*)&a2[64 + 2 * lane];
    float es = z.x * as.x + z.y * as.y;
    float ed = z.x * ad.x + z.y * ad.y;
    #pragma unroll
    for (int o = 16; o; o >>= 1) {
        es += __shfl_xor_sync(0xffffffffu, es, o);
        ed += __shfl_xor_sync(0xffffffffu, ed, o);
    }
    if (lane == 0) { g_es2[n] = es; g_ed2[n] = ed; }
}

// ---------------- layer-2 aggregation (warp per node) -> output --------------
__global__ void k_agg2(float* __restrict__ out) {
    __shared__ float s_ex[8][32];
    int gw = (blockIdx.x * blockDim.x + threadIdx.x) >> 5;
    int lane = threadIdx.x & 31;
    int w = threadIdx.x >> 5;
    if (gw >= N_NODES) return;
    int n = gw;
    int off = g_off[n];
    int deg = g_off[n + 1] - off;

    float edv = g_ed2[n];
    float m = -1e30f;
    for (int i = off + lane; i < off + deg; i += 32) {
        int s = g_ssrc[i];
        m = fmaxf(m, leaky(g_es2[s] + edv));
    }
    #pragma unroll
    for (int o = 16; o; o >>= 1) m = fmaxf(m, __shfl_xor_sync(0xffffffffu, m, o));

    float2 acc = make_float2(0.f, 0.f);
    float dsum = 0.f;
    for (int i = off; i < off + deg; i += 32) {
        int nb = off + deg - i; if (nb > 32) nb = 32;
        int s_l = 0;
        float ex_l = 0.f;
        if (lane < nb) {
            s_l = g_ssrc[i + lane];
            ex_l = __expf(leaky(g_es2[s_l] + edv) - m);
        }
        s_ex[w][lane] = ex_l;
        __syncwarp();
        #pragma unroll 4
        for (int t = 0; t < nb; t++) {
            int s = __shfl_sync(0xffffffffu, s_l, t);
            float ex = s_ex[w][t];
            const float2 z = *(const float2*)&g_z2[s * 64 + 2 * lane];
            dsum += ex;
            acc.x += ex * z.x;
            acc.y += ex * z.y;
        }
        __syncwarp();
    }
    float inv = (deg > 0) ? (1.0f / dsum) : 0.f;
    float2 o;
    o.x = acc.x * inv;
    o.y = acc.y * inv;
    *(float2*)&out[n * 64 + 2 * lane] = o;
}

// ---------------- launch -----------------------------------------------------
extern "C" void kernel_launch(void* const* d_in, const int* in_sizes, int n_in,
                              void* d_out, int out_size) {
    const float* h   = (const float*)d_in[0];
    const int*   src = (const int*)  d_in[1];
    const int*   dst = (const int*)  d_in[2];
    const float* W1  = (const float*)d_in[3];
    const float* a1  = (const float*)d_in[4];
    const float* W2  = (const float*)d_in[5];
    const float* a2  = (const float*)d_in[6];
    float* out = (float*)d_out;

    const int SMEM1 = (256 * 128 + 64 * 256) * 4;   // 196608
    const int SMEM2 = (128 * 64 + 128 * 128) * 4;   //  98304
    cudaFuncSetAttribute(k_gemm1, cudaFuncAttributeMaxDynamicSharedMemorySize, SMEM1);
    cudaFuncSetAttribute(k_gemm2, cudaFuncAttributeMaxDynamicSharedMemorySize, SMEM2);

    // CSR build (dst shared by both layers)
    k_zero   <<<(N_NODES + 255) / 256, 256>>>();
    k_hist   <<<(N_EDGES + 255) / 256, 256>>>(dst);
    k_scan   <<<1, 1024>>>();
    k_scatter<<<(N_EDGES + 255) / 256, 256>>>(src, dst);

    // layer 1
    k_gemm1<<<152, 512, SMEM1>>>(h, W1);
    k_att1 <<<(N_NODES + 7) / 8, 256>>>(a1);
    k_agg1 <<<(N_NODES + 7) / 8, 256>>>();

    // layer 2
    k_gemm2<<<152, 512, SMEM2>>>(W2);
    k_att2 <<<(N_NODES + 7) / 8, 256>>>(a2);
    k_agg2 <<<(N_NODES + 7) / 8, 256>>>(out);
}

// round 6
// speedup vs baseline: 1.2564x; 1.2564x over previous
#include <cuda_runtime.h>
#include <math.h>

#define N_NODES 50000
#define N_EDGES 800000
#define IN_DIM  256
#define C1      128     // HEADS * 32
#define HEADS   4
#define HID1    32
#define OUT_DIM 64

typedef unsigned long long u64;

// ---------------- scratch (device globals; no allocation allowed) ------------
__device__ __align__(16) float g_z1 [N_NODES * C1];
__device__ __align__(16) float g_es1[N_NODES * HEADS];
__device__ __align__(16) float g_ed1[N_NODES * HEADS];
__device__ __align__(16) float g_h1 [N_NODES * C1];
__device__ __align__(16) float g_z2 [N_NODES * OUT_DIM];
__device__ float g_es2[N_NODES];
__device__ float g_ed2[N_NODES];
__device__ int   g_deg[N_NODES];
__device__ int   g_pos[N_NODES];
__device__ int   g_off[N_NODES + 1];
__device__ int   g_ssrc[N_EDGES];

__device__ __forceinline__ float leaky(float x) { return x > 0.f ? x : 0.01f * x; }
__device__ __forceinline__ float elu_f(float x) { return x > 0.f ? x : (__expf(x) - 1.f); }

// packed fp32x2 FMA (sm_100+): d = a*b + c elementwise on 2 packed floats
__device__ __forceinline__ u64 ffma2(u64 a, u64 b, u64 c) {
    u64 d;
    asm("fma.rn.f32x2 %0, %1, %2, %3;" : "=l"(d) : "l"(a), "l"(b), "l"(c));
    return d;
}
// duplicate one fp32 into both lanes of a packed f32x2
__device__ __forceinline__ u64 dup2(float x) {
    u64 d; unsigned b = __float_as_uint(x);
    asm("mov.b64 %0, {%1, %1};" : "=l"(d) : "r"(b));
    return d;
}

// ---------------- CSR build --------------------------------------------------
__global__ void k_zero() {
    int i = blockIdx.x * blockDim.x + threadIdx.x;
    if (i < N_NODES) { g_deg[i] = 0; g_pos[i] = 0; }
}

__global__ void k_hist(const int* __restrict__ dst) {
    int e = blockIdx.x * blockDim.x + threadIdx.x;
    if (e < N_EDGES) atomicAdd(&g_deg[dst[e]], 1);
}

__global__ void k_scan() {
    __shared__ int sm[1024];
    int tid = threadIdx.x;
    const int CH = (N_NODES + 1023) / 1024;   // 49
    int base = tid * CH;
    int s = 0;
    for (int i = 0; i < CH; i++) {
        int idx = base + i;
        if (idx < N_NODES) s += g_deg[idx];
    }
    sm[tid] = s;
    __syncthreads();
    for (int d = 1; d < 1024; d <<= 1) {
        int v = (tid >= d) ? sm[tid - d] : 0;
        __syncthreads();
        sm[tid] += v;
        __syncthreads();
    }
    int run = sm[tid] - s;   // exclusive prefix
    for (int i = 0; i < CH; i++) {
        int idx = base + i;
        if (idx < N_NODES) { g_off[idx] = run; run += g_deg[idx]; }
    }
    if (tid == 1023) g_off[N_NODES] = sm[1023];
}

__global__ void k_scatter(const int* __restrict__ src, const int* __restrict__ dst) {
    int e = blockIdx.x * blockDim.x + threadIdx.x;
    if (e < N_EDGES) {
        int d = dst[e];
        int p = g_off[d] + atomicAdd(&g_pos[d], 1);
        g_ssrc[p] = src[e];
    }
}

// ---------------- layer-1 GEMM: z1 = h @ W1 (256 -> 128) ---------------------
// sW[k][c] natural layout (conflict-free LDS.128), sx[n][k].
// Thread tile 8 nodes x 4 cols; accumulators packed f32x2 over column pairs.
__global__ void __launch_bounds__(256, 1) k_gemm1(const float* __restrict__ x,
                                                  const float* __restrict__ W1) {
    extern __shared__ float sm[];
    float* sW = sm;                  // 256*128 floats
    float* sx = sm + 256 * 128;      // 64*256 floats
    int tid = threadIdx.x;           // 256 threads

    // W1 [h][k][d] -> sW[k][h*32+d]
    for (int i = tid; i < HEADS * IN_DIM * HID1; i += 256) {
        int hh = i >> 13, k = (i >> 5) & 255, d = i & 31;
        sW[k * 128 + hh * 32 + d] = W1[i];
    }

    int c0 = (tid & 31) * 4;          // lane-varying col group (conflict-free)
    int nr = (tid >> 5) * 8;          // warp-uniform node group (broadcast)
    int ntiles = (N_NODES + 63) >> 6;

    for (int tile = blockIdx.x; tile < ntiles; tile += gridDim.x) {
        int n0 = tile << 6;
        __syncthreads();
        for (int i = tid; i < 64 * 64; i += 256) {
            int n = n0 + (i >> 6);
            float4 v = make_float4(0.f, 0.f, 0.f, 0.f);
            if (n < N_NODES) v = ((const float4*)x)[n * 64 + (i & 63)];
            ((float4*)sx)[i] = v;
        }
        __syncthreads();

        u64 acc[8][2];
        #pragma unroll
        for (int j = 0; j < 8; j++) { acc[j][0] = 0ull; acc[j][1] = 0ull; }

        const float* xs = sx + nr * 256;
        #pragma unroll 2
        for (int k = 0; k < 256; k += 4) {
            ulonglong2 wp[4];
            #pragma unroll
            for (int kk = 0; kk < 4; kk++)
                wp[kk] = *(const ulonglong2*)&sW[(k + kk) * 128 + c0];
            #pragma unroll
            for (int j = 0; j < 8; j++) {
                float4 xv = *(const float4*)&xs[j * 256 + k];
                u64 x0 = dup2(xv.x), x1 = dup2(xv.y);
                u64 x2 = dup2(xv.z), x3 = dup2(xv.w);
                acc[j][0] = ffma2(x0, wp[0].x, acc[j][0]);
                acc[j][1] = ffma2(x0, wp[0].y, acc[j][1]);
                acc[j][0] = ffma2(x1, wp[1].x, acc[j][0]);
                acc[j][1] = ffma2(x1, wp[1].y, acc[j][1]);
                acc[j][0] = ffma2(x2, wp[2].x, acc[j][0]);
                acc[j][1] = ffma2(x2, wp[2].y, acc[j][1]);
                acc[j][0] = ffma2(x3, wp[3].x, acc[j][0]);
                acc[j][1] = ffma2(x3, wp[3].y, acc[j][1]);
            }
        }

        #pragma unroll
        for (int j = 0; j < 8; j++) {
            int n = n0 + nr + j;
            if (n < N_NODES) {
                ulonglong2 o; o.x = acc[j][0]; o.y = acc[j][1];
                *(ulonglong2*)&g_z1[n * 128 + c0] = o;
            }
        }
    }
}

// ---------------- layer-1 attention coefficients -----------------------------
__global__ void k_att1(const float* __restrict__ a1) {
    int gw = (blockIdx.x * blockDim.x + threadIdx.x) >> 5;
    if (gw >= N_NODES) return;
    int lane = threadIdx.x & 31;
    int n = gw;
    const float4 z = *(const float4*)&g_z1[n * 128 + 4 * lane];
    int h  = lane >> 3;
    int d0 = (lane & 7) * 4;
    const float* ap = a1 + h * 64;
    float4 as = *(const float4*)&ap[d0];
    float4 ad = *(const float4*)&ap[32 + d0];
    float es = z.x * as.x + z.y * as.y + z.z * as.z + z.w * as.w;
    float ed = z.x * ad.x + z.y * ad.y + z.z * ad.z + z.w * ad.w;
    #pragma unroll
    for (int o = 4; o; o >>= 1) {
        es += __shfl_xor_sync(0xffffffffu, es, o);
        ed += __shfl_xor_sync(0xffffffffu, ed, o);
    }
    if ((lane & 7) == 0) {
        g_es1[n * 4 + h] = es;
        g_ed1[n * 4 + h] = ed;
    }
}

// ---------------- layer-1 aggregation (warp per node) + ELU ------------------
__global__ void k_agg1() {
    __shared__ float s_ex[8][128];
    int gw = (blockIdx.x * blockDim.x + threadIdx.x) >> 5;
    int lane = threadIdx.x & 31;
    int w = threadIdx.x >> 5;
    if (gw >= N_NODES) return;
    int n = gw;
    int off = g_off[n];
    int deg = g_off[n + 1] - off;

    const float4 ed4 = *(const float4*)&g_ed1[n * 4];

    // pass 1: per-head max
    float4 m4 = make_float4(-1e30f, -1e30f, -1e30f, -1e30f);
    for (int i = off + lane; i < off + deg; i += 32) {
        int s = g_ssrc[i];
        float4 es4 = *(const float4*)&g_es1[s * 4];
        m4.x = fmaxf(m4.x, leaky(es4.x + ed4.x));
        m4.y = fmaxf(m4.y, leaky(es4.y + ed4.y));
        m4.z = fmaxf(m4.z, leaky(es4.z + ed4.z));
        m4.w = fmaxf(m4.w, leaky(es4.w + ed4.w));
    }
    #pragma unroll
    for (int o = 16; o; o >>= 1) {
        m4.x = fmaxf(m4.x, __shfl_xor_sync(0xffffffffu, m4.x, o));
        m4.y = fmaxf(m4.y, __shfl_xor_sync(0xffffffffu, m4.y, o));
        m4.z = fmaxf(m4.z, __shfl_xor_sync(0xffffffffu, m4.z, o));
        m4.w = fmaxf(m4.w, __shfl_xor_sync(0xffffffffu, m4.w, o));
    }

    // pass 2: fused softmax + weighted aggregation
    float4 acc = make_float4(0.f, 0.f, 0.f, 0.f);
    float dsum = 0.f;
    int hl = lane >> 3;
    for (int i = off; i < off + deg; i += 32) {
        int nb = off + deg - i; if (nb > 32) nb = 32;
        int s_l = 0;
        float4 ex4 = make_float4(0.f, 0.f, 0.f, 0.f);
        if (lane < nb) {
            s_l = g_ssrc[i + lane];
            float4 es4 = *(const float4*)&g_es1[s_l * 4];
            ex4.x = __expf(leaky(es4.x + ed4.x) - m4.x);
            ex4.y = __expf(leaky(es4.y + ed4.y) - m4.y);
            ex4.z = __expf(leaky(es4.z + ed4.z) - m4.z);
            ex4.w = __expf(leaky(es4.w + ed4.w) - m4.w);
        }
        *(float4*)&s_ex[w][lane * 4] = ex4;
        __syncwarp();
        #pragma unroll 4
        for (int t = 0; t < nb; t++) {
            int s = __shfl_sync(0xffffffffu, s_l, t);
            float ex = s_ex[w][t * 4 + hl];
            const float4 z = *(const float4*)&g_z1[s * 128 + 4 * lane];
            dsum += ex;
            acc.x += ex * z.x;
            acc.y += ex * z.y;
            acc.z += ex * z.z;
            acc.w += ex * z.w;
        }
        __syncwarp();
    }
    float inv = (deg > 0) ? (1.0f / dsum) : 0.f;
    float4 o;
    o.x = elu_f(acc.x * inv);
    o.y = elu_f(acc.y * inv);
    o.z = elu_f(acc.z * inv);
    o.w = elu_f(acc.w * inv);
    *(float4*)&g_h1[n * 128 + 4 * lane] = o;
}

// ---------------- layer-2 GEMM: z2 = h1 @ W2 (128 -> 64) ---------------------
// sW2[k][c] natural layout, sx[n][k]. Thread tile 4 nodes x 4 cols, f32x2 col-pairs.
__global__ void __launch_bounds__(256) k_gemm2(const float* __restrict__ W2) {
    extern __shared__ float sm[];
    float* sW = sm;                 // 128*64 floats
    float* sx = sm + 128 * 64;      // 64*128 floats
    int tid = threadIdx.x;          // 256 threads

    for (int i = tid; i < 128 * 64; i += 256) sW[i] = W2[i];

    int c0 = (tid & 15) * 4;        // 16 col-groups of 4
    int nr = (tid >> 4) * 4;        // 16 node-groups of 4
    int ntiles = (N_NODES + 63) >> 6;

    for (int tile = blockIdx.x; tile < ntiles; tile += gridDim.x) {
        int n0 = tile << 6;
        __syncthreads();
        for (int i = tid; i < 64 * 32; i += 256) {
            int n = n0 + (i >> 5);
            float4 v = make_float4(0.f, 0.f, 0.f, 0.f);
            if (n < N_NODES) v = ((const float4*)g_h1)[n * 32 + (i & 31)];
            ((float4*)sx)[i] = v;
        }
        __syncthreads();

        u64 acc[4][2];
        #pragma unroll
        for (int j = 0; j < 4; j++) { acc[j][0] = 0ull; acc[j][1] = 0ull; }

        const float* xs = sx + nr * 128;
        #pragma unroll 2
        for (int k = 0; k < 128; k += 4) {
            ulonglong2 wp[4];
            #pragma unroll
            for (int kk = 0; kk < 4; kk++)
                wp[kk] = *(const ulonglong2*)&sW[(k + kk) * 64 + c0];
            #pragma unroll
            for (int j = 0; j < 4; j++) {
                float4 xv = *(const float4*)&xs[j * 128 + k];
                u64 x0 = dup2(xv.x), x1 = dup2(xv.y);
                u64 x2 = dup2(xv.z), x3 = dup2(xv.w);
                acc[j][0] = ffma2(x0, wp[0].x, acc[j][0]);
                acc[j][1] = ffma2(x0, wp[0].y, acc[j][1]);
                acc[j][0] = ffma2(x1, wp[1].x, acc[j][0]);
                acc[j][1] = ffma2(x1, wp[1].y, acc[j][1]);
                acc[j][0] = ffma2(x2, wp[2].x, acc[j][0]);
                acc[j][1] = ffma2(x2, wp[2].y, acc[j][1]);
                acc[j][0] = ffma2(x3, wp[3].x, acc[j][0]);
                acc[j][1] = ffma2(x3, wp[3].y, acc[j][1]);
            }
        }

        #pragma unroll
        for (int j = 0; j < 4; j++) {
            int n = n0 + nr + j;
            if (n < N_NODES) {
                ulonglong2 o; o.x = acc[j][0]; o.y = acc[j][1];
                *(ulonglong2*)&g_z2[n * 64 + c0] = o;
            }
        }
    }
}

// ---------------- layer-2 attention coefficients -----------------------------
__global__ void k_att2(const float* __restrict__ a2) {
    int gw = (blockIdx.x * blockDim.x + threadIdx.x) >> 5;
    if (gw >= N_NODES) return;
    int lane = threadIdx.x & 31;
    int n = gw;
    const float2 z = *(const float2*)&g_z2[n * 64 + 2 * lane];
    float2 as = *(const float2*)&a2[2 * lane];
    float2 ad = *(const float2*)&a2[64 + 2 * lane];
    float es = z.x * as.x + z.y * as.y;
    float ed = z.x * ad.x + z.y * ad.y;
    #pragma unroll
    for (int o = 16; o; o >>= 1) {
        es += __shfl_xor_sync(0xffffffffu, es, o);
        ed += __shfl_xor_sync(0xffffffffu, ed, o);
    }
    if (lane == 0) { g_es2[n] = es; g_ed2[n] = ed; }
}

// ---------------- layer-2 aggregation (warp per node) -> output --------------
__global__ void k_agg2(float* __restrict__ out) {
    __shared__ float s_ex[8][32];
    int gw = (blockIdx.x * blockDim.x + threadIdx.x) >> 5;
    int lane = threadIdx.x & 31;
    int w = threadIdx.x >> 5;
    if (gw >= N_NODES) return;
    int n = gw;
    int off = g_off[n];
    int deg = g_off[n + 1] - off;

    float edv = g_ed2[n];
    float m = -1e30f;
    for (int i = off + lane; i < off + deg; i += 32) {
        int s = g_ssrc[i];
        m = fmaxf(m, leaky(g_es2[s] + edv));
    }
    #pragma unroll
    for (int o = 16; o; o >>= 1) m = fmaxf(m, __shfl_xor_sync(0xffffffffu, m, o));

    float2 acc = make_float2(0.f, 0.f);
    float dsum = 0.f;
    for (int i = off; i < off + deg; i += 32) {
        int nb = off + deg - i; if (nb > 32) nb = 32;
        int s_l = 0;
        float ex_l = 0.f;
        if (lane < nb) {
            s_l = g_ssrc[i + lane];
            ex_l = __expf(leaky(g_es2[s_l] + edv) - m);
        }
        s_ex[w][lane] = ex_l;
        __syncwarp();
        #pragma unroll 4
        for (int t = 0; t < nb; t++) {
            int s = __shfl_sync(0xffffffffu, s_l, t);
            float ex = s_ex[w][t];
            const float2 z = *(const float2*)&g_z2[s * 64 + 2 * lane];
            dsum += ex;
            acc.x += ex * z.x;
            acc.y += ex * z.y;
        }
        __syncwarp();
    }
    float inv = (deg > 0) ? (1.0f / dsum) : 0.f;
    float2 o;
    o.x = acc.x * inv;
    o.y = acc.y * inv;
    *(float2*)&out[n * 64 + 2 * lane] = o;
}

// ---------------- launch -----------------------------------------------------
extern "C" void kernel_launch(void* const* d_in, const int* in_sizes, int n_in,
                              void* d_out, int out_size) {
    const float* h   = (const float*)d_in[0];
    const int*   src = (const int*)  d_in[1];
    const int*   dst = (const int*)  d_in[2];
    const float* W1  = (const float*)d_in[3];
    const float* a1  = (const float*)d_in[4];
    const float* W2  = (const float*)d_in[5];
    const float* a2  = (const float*)d_in[6];
    float* out = (float*)d_out;

    const int SMEM1 = (256 * 128 + 64 * 256) * 4;   // 196608
    const int SMEM2 = (128 * 64 + 64 * 128) * 4;    //  65536
    cudaFuncSetAttribute(k_gemm1, cudaFuncAttributeMaxDynamicSharedMemorySize, SMEM1);
    cudaFuncSetAttribute(k_gemm2, cudaFuncAttributeMaxDynamicSharedMemorySize, SMEM2);

    // CSR build (dst shared by both layers)
    k_zero   <<<(N_NODES + 255) / 256, 256>>>();
    k_hist   <<<(N_EDGES + 255) / 256, 256>>>(dst);
    k_scan   <<<1, 1024>>>();
    k_scatter<<<(N_EDGES + 255) / 256, 256>>>(src, dst);

    // layer 1
    k_gemm1<<<148, 256, SMEM1>>>(h, W1);
    k_att1 <<<(N_NODES + 7) / 8, 256>>>(a1);
    k_agg1 <<<(N_NODES + 7) / 8, 256>>>();

    // layer 2
    k_gemm2<<<296, 256, SMEM2>>>(W2);
    k_att2 <<<(N_NODES + 7) / 8, 256>>>(a2);
    k_agg2 <<<(N_NODES + 7) / 8, 256>>>(out);
}

// round 11
// speedup vs baseline: 1.5845x; 1.2611x over previous
#include <cuda_runtime.h>
#include <math.h>

#define N_NODES 50000
#define N_EDGES 800000
#define IN_DIM  256
#define C1      128     // HEADS * 32
#define HEADS   4
#define HID1    32
#define OUT_DIM 64

typedef unsigned long long u64;

// ---------------- scratch (device globals; no allocation allowed) ------------
__device__ __align__(16) float g_z1 [N_NODES * C1];
__device__ __align__(16) float g_es1[N_NODES * HEADS];
__device__ __align__(16) float g_ed1[N_NODES * HEADS];
__device__ __align__(16) float g_h1 [N_NODES * C1];
__device__ __align__(16) float g_z2 [N_NODES * OUT_DIM];
__device__ float g_es2[N_NODES];
__device__ float g_ed2[N_NODES];
__device__ int   g_deg[N_NODES];
__device__ int   g_pos[N_NODES];
__device__ int   g_off[N_NODES + 1];
__device__ int   g_ssrc[N_EDGES];

__device__ __forceinline__ float leaky(float x) { return x > 0.f ? x : 0.01f * x; }
__device__ __forceinline__ float elu_f(float x) { return x > 0.f ? x : (__expf(x) - 1.f); }

// packed fp32x2 FMA (sm_100+): d = a*b + c elementwise on 2 packed floats
__device__ __forceinline__ u64 ffma2(u64 a, u64 b, u64 c) {
    u64 d;
    asm("fma.rn.f32x2 %0, %1, %2, %3;" : "=l"(d) : "l"(a), "l"(b), "l"(c));
    return d;
}
// duplicate one fp32 into both lanes of a packed f32x2
__device__ __forceinline__ u64 dup2(float x) {
    u64 d; unsigned b = __float_as_uint(x);
    asm("mov.b64 %0, {%1, %1};" : "=l"(d) : "r"(b));
    return d;
}
__device__ __forceinline__ float f2lo(u64 v) { return __uint_as_float((unsigned)v); }
__device__ __forceinline__ float f2hi(u64 v) { return __uint_as_float((unsigned)(v >> 32)); }

// ---------------- CSR build --------------------------------------------------
__global__ void k_zero() {
    int i = blockIdx.x * blockDim.x + threadIdx.x;
    if (i < N_NODES) { g_deg[i] = 0; g_pos[i] = 0; }
}

__global__ void k_hist(const int* __restrict__ dst) {
    int e = blockIdx.x * blockDim.x + threadIdx.x;
    if (e < N_EDGES) atomicAdd(&g_deg[dst[e]], 1);
}

__global__ void k_scan() {
    __shared__ int sm[1024];
    int tid = threadIdx.x;
    const int CH = (N_NODES + 1023) / 1024;   // 49
    int base = tid * CH;
    int s = 0;
    for (int i = 0; i < CH; i++) {
        int idx = base + i;
        if (idx < N_NODES) s += g_deg[idx];
    }
    sm[tid] = s;
    __syncthreads();
    for (int d = 1; d < 1024; d <<= 1) {
        int v = (tid >= d) ? sm[tid - d] : 0;
        __syncthreads();
        sm[tid] += v;
        __syncthreads();
    }
    int run = sm[tid] - s;   // exclusive prefix
    for (int i = 0; i < CH; i++) {
        int idx = base + i;
        if (idx < N_NODES) { g_off[idx] = run; run += g_deg[idx]; }
    }
    if (tid == 1023) g_off[N_NODES] = sm[1023];
}

__global__ void k_scatter(const int* __restrict__ src, const int* __restrict__ dst) {
    int e = blockIdx.x * blockDim.x + threadIdx.x;
    if (e < N_EDGES) {
        int d = dst[e];
        int p = g_off[d] + atomicAdd(&g_pos[d], 1);
        g_ssrc[p] = src[e];
    }
}

// ---------------- layer-1 GEMM + attention coeffs (fused) --------------------
// sW[k][c] natural layout (conflict-free LDS.128), sx[n][k].
// Thread tile 8 nodes x 4 cols; accumulators packed f32x2 over column pairs.
// Epilogue computes es/ed per (node, head) via 8-lane shfl reduction.
__global__ void __launch_bounds__(256, 1) k_gemm1(const float* __restrict__ x,
                                                  const float* __restrict__ W1,
                                                  const float* __restrict__ a1) {
    extern __shared__ float sm[];
    float* sW = sm;                  // 256*128 floats
    float* sx = sm + 256 * 128;      // 64*256 floats
    int tid = threadIdx.x;           // 256 threads

    // W1 [h][k][d] -> sW[k][h*32+d]
    for (int i = tid; i < HEADS * IN_DIM * HID1; i += 256) {
        int hh = i >> 13, k = (i >> 5) & 255, d = i & 31;
        sW[k * 128 + hh * 32 + d] = W1[i];
    }

    int lane = tid & 31;
    int c0 = lane * 4;                // lane-varying col group (conflict-free)
    int nr = (tid >> 5) * 8;          // warp-uniform node group (broadcast)
    int hl = lane >> 3;               // head owned by this lane
    int d0 = c0 & 31;                 // offset within head
    const float4 as4 = *(const float4*)&a1[hl * 64 + d0];
    const float4 ad4 = *(const float4*)&a1[hl * 64 + 32 + d0];
    int ntiles = (N_NODES + 63) >> 6;

    for (int tile = blockIdx.x; tile < ntiles; tile += gridDim.x) {
        int n0 = tile << 6;
        __syncthreads();
        for (int i = tid; i < 64 * 64; i += 256) {
            int n = n0 + (i >> 6);
            float4 v = make_float4(0.f, 0.f, 0.f, 0.f);
            if (n < N_NODES) v = ((const float4*)x)[n * 64 + (i & 63)];
            ((float4*)sx)[i] = v;
        }
        __syncthreads();

        u64 acc[8][2];
        #pragma unroll
        for (int j = 0; j < 8; j++) { acc[j][0] = 0ull; acc[j][1] = 0ull; }

        const float* xs = sx + nr * 256;
        #pragma unroll 2
        for (int k = 0; k < 256; k += 4) {
            ulonglong2 wp[4];
            #pragma unroll
            for (int kk = 0; kk < 4; kk++)
                wp[kk] = *(const ulonglong2*)&sW[(k + kk) * 128 + c0];
            #pragma unroll
            for (int j = 0; j < 8; j++) {
                float4 xv = *(const float4*)&xs[j * 256 + k];
                u64 x0 = dup2(xv.x), x1 = dup2(xv.y);
                u64 x2 = dup2(xv.z), x3 = dup2(xv.w);
                acc[j][0] = ffma2(x0, wp[0].x, acc[j][0]);
                acc[j][1] = ffma2(x0, wp[0].y, acc[j][1]);
                acc[j][0] = ffma2(x1, wp[1].x, acc[j][0]);
                acc[j][1] = ffma2(x1, wp[1].y, acc[j][1]);
                acc[j][0] = ffma2(x2, wp[2].x, acc[j][0]);
                acc[j][1] = ffma2(x2, wp[2].y, acc[j][1]);
                acc[j][0] = ffma2(x3, wp[3].x, acc[j][0]);
                acc[j][1] = ffma2(x3, wp[3].y, acc[j][1]);
            }
        }

        #pragma unroll
        for (int j = 0; j < 8; j++) {
            int n = n0 + nr + j;          // warp-uniform
            float4 o;
            o.x = f2lo(acc[j][0]); o.y = f2hi(acc[j][0]);
            o.z = f2lo(acc[j][1]); o.w = f2hi(acc[j][1]);
            float es = o.x * as4.x + o.y * as4.y + o.z * as4.z + o.w * as4.w;
            float ed = o.x * ad4.x + o.y * ad4.y + o.z * ad4.z + o.w * ad4.w;
            #pragma unroll
            for (int m = 4; m; m >>= 1) {
                es += __shfl_xor_sync(0xffffffffu, es, m);
                ed += __shfl_xor_sync(0xffffffffu, ed, m);
            }
            if (n < N_NODES) {
                ulonglong2 ov; ov.x = acc[j][0]; ov.y = acc[j][1];
                *(ulonglong2*)&g_z1[n * 128 + c0] = ov;
                if ((lane & 7) == 0) {
                    g_es1[n * 4 + hl] = es;
                    g_ed1[n * 4 + hl] = ed;
                }
            }
        }
    }
}

// ---------------- layer-1 aggregation (warp per node) + ELU ------------------
__global__ void k_agg1() {
    __shared__ float s_ex[8][128];
    int gw = (blockIdx.x * blockDim.x + threadIdx.x) >> 5;
    int lane = threadIdx.x & 31;
    int w = threadIdx.x >> 5;
    if (gw >= N_NODES) return;
    int n = gw;
    int off = g_off[n];
    int deg = g_off[n + 1] - off;

    const float4 ed4 = *(const float4*)&g_ed1[n * 4];

    // pass 1: per-head max
    float4 m4 = make_float4(-1e30f, -1e30f, -1e30f, -1e30f);
    for (int i = off + lane; i < off + deg; i += 32) {
        int s = g_ssrc[i];
        float4 es4 = *(const float4*)&g_es1[s * 4];
        m4.x = fmaxf(m4.x, leaky(es4.x + ed4.x));
        m4.y = fmaxf(m4.y, leaky(es4.y + ed4.y));
        m4.z = fmaxf(m4.z, leaky(es4.z + ed4.z));
        m4.w = fmaxf(m4.w, leaky(es4.w + ed4.w));
    }
    #pragma unroll
    for (int o = 16; o; o >>= 1) {
        m4.x = fmaxf(m4.x, __shfl_xor_sync(0xffffffffu, m4.x, o));
        m4.y = fmaxf(m4.y, __shfl_xor_sync(0xffffffffu, m4.y, o));
        m4.z = fmaxf(m4.z, __shfl_xor_sync(0xffffffffu, m4.z, o));
        m4.w = fmaxf(m4.w, __shfl_xor_sync(0xffffffffu, m4.w, o));
    }

    // pass 2: fused softmax + weighted aggregation
    float4 acc = make_float4(0.f, 0.f, 0.f, 0.f);
    float dsum = 0.f;
    int hl = lane >> 3;
    for (int i = off; i < off + deg; i += 32) {
        int nb = off + deg - i; if (nb > 32) nb = 32;
        int s_l = 0;
        float4 ex4 = make_float4(0.f, 0.f, 0.f, 0.f);
        if (lane < nb) {
            s_l = g_ssrc[i + lane];
            float4 es4 = *(const float4*)&g_es1[s_l * 4];
            ex4.x = __expf(leaky(es4.x + ed4.x) - m4.x);
            ex4.y = __expf(leaky(es4.y + ed4.y) - m4.y);
            ex4.z = __expf(leaky(es4.z + ed4.z) - m4.z);
            ex4.w = __expf(leaky(es4.w + ed4.w) - m4.w);
        }
        *(float4*)&s_ex[w][lane * 4] = ex4;
        __syncwarp();
        #pragma unroll 4
        for (int t = 0; t < nb; t++) {
            int s = __shfl_sync(0xffffffffu, s_l, t);
            float ex = s_ex[w][t * 4 + hl];
            const float4 z = *(const float4*)&g_z1[s * 128 + 4 * lane];
            dsum += ex;
            acc.x += ex * z.x;
            acc.y += ex * z.y;
            acc.z += ex * z.z;
            acc.w += ex * z.w;
        }
        __syncwarp();
    }
    float inv = (deg > 0) ? (1.0f / dsum) : 0.f;
    float4 o;
    o.x = elu_f(acc.x * inv);
    o.y = elu_f(acc.y * inv);
    o.z = elu_f(acc.z * inv);
    o.w = elu_f(acc.w * inv);
    *(float4*)&g_h1[n * 128 + 4 * lane] = o;
}

// ---------------- layer-2 GEMM + attention coeffs (fused) --------------------
// sW2[k][c] natural layout, sx[n][k]. Thread tile 4 nodes x 4 cols.
// Epilogue: es2/ed2 per node via 16-lane (half-warp) shfl reduction.
__global__ void __launch_bounds__(256) k_gemm2(const float* __restrict__ W2,
                                               const float* __restrict__ a2) {
    extern __shared__ float sm[];
    float* sW = sm;                 // 128*64 floats
    float* sx = sm + 128 * 64;      // 64*128 floats
    int tid = threadIdx.x;          // 256 threads

    for (int i = tid; i < 128 * 64; i += 256) sW[i] = W2[i];

    int lane = tid & 31;
    int c0 = (tid & 15) * 4;        // 16 col-groups of 4
    int nr = (tid >> 4) * 4;        // 16 node-groups of 4 (uniform per half-warp)
    const float4 as4 = *(const float4*)&a2[c0];
    const float4 ad4 = *(const float4*)&a2[64 + c0];
    int ntiles = (N_NODES + 63) >> 6;

    for (int tile = blockIdx.x; tile < ntiles; tile += gridDim.x) {
        int n0 = tile << 6;
        __syncthreads();
        for (int i = tid; i < 64 * 32; i += 256) {
            int n = n0 + (i >> 5);
            float4 v = make_float4(0.f, 0.f, 0.f, 0.f);
            if (n < N_NODES) v = ((const float4*)g_h1)[n * 32 + (i & 31)];
            ((float4*)sx)[i] = v;
        }
        __syncthreads();

        u64 acc[4][2];
        #pragma unroll
        for (int j = 0; j < 4; j++) { acc[j][0] = 0ull; acc[j][1] = 0ull; }

        const float* xs = sx + nr * 128;
        #pragma unroll 2
        for (int k = 0; k < 128; k += 4) {
            ulonglong2 wp[4];
            #pragma unroll
            for (int kk = 0; kk < 4; kk++)
                wp[kk] = *(const ulonglong2*)&sW[(k + kk) * 64 + c0];
            #pragma unroll
            for (int j = 0; j < 4; j++) {
                float4 xv = *(const float4*)&xs[j * 128 + k];
                u64 x0 = dup2(xv.x), x1 = dup2(xv.y);
                u64 x2 = dup2(xv.z), x3 = dup2(xv.w);
                acc[j][0] = ffma2(x0, wp[0].x, acc[j][0]);
                acc[j][1] = ffma2(x0, wp[0].y, acc[j][1]);
                acc[j][0] = ffma2(x1, wp[1].x, acc[j][0]);
                acc[j][1] = ffma2(x1, wp[1].y, acc[j][1]);
                acc[j][0] = ffma2(x2, wp[2].x, acc[j][0]);
                acc[j][1] = ffma2(x2, wp[2].y, acc[j][1]);
                acc[j][0] = ffma2(x3, wp[3].x, acc[j][0]);
                acc[j][1] = ffma2(x3, wp[3].y, acc[j][1]);
            }
        }

        #pragma unroll
        for (int j = 0; j < 4; j++) {
            int n = n0 + nr + j;      // uniform per half-warp
            float4 o;
            o.x = f2lo(acc[j][0]); o.y = f2hi(acc[j][0]);
            o.z = f2lo(acc[j][1]); o.w = f2hi(acc[j][1]);
            float es = o.x * as4.x + o.y * as4.y + o.z * as4.z + o.w * as4.w;
            float ed = o.x * ad4.x + o.y * ad4.y + o.z * ad4.z + o.w * ad4.w;
            #pragma unroll
            for (int m = 8; m; m >>= 1) {
                es += __shfl_xor_sync(0xffffffffu, es, m);
                ed += __shfl_xor_sync(0xffffffffu, ed, m);
            }
            if (n < N_NODES) {
                ulonglong2 ov; ov.x = acc[j][0]; ov.y = acc[j][1];
                *(ulonglong2*)&g_z2[n * 64 + c0] = ov;
                if ((lane & 15) == 0) {
                    g_es2[n] = es;
                    g_ed2[n] = ed;
                }
            }
        }
    }
}

// ---------------- layer-2 aggregation (warp per node) -> output --------------
__global__ void k_agg2(float* __restrict__ out) {
    __shared__ float s_ex[8][32];
    int gw = (blockIdx.x * blockDim.x + threadIdx.x) >> 5;
    int lane = threadIdx.x & 31;
    int w = threadIdx.x >> 5;
    if (gw >= N_NODES) return;
    int n = gw;
    int off = g_off[n];
    int deg = g_off[n + 1] - off;

    float edv = g_ed2[n];
    float m = -1e30f;
    for (int i = off + lane; i < off + deg; i += 32) {
        int s = g_ssrc[i];
        m = fmaxf(m, leaky(g_es2[s] + edv));
    }
    #pragma unroll
    for (int o = 16; o; o >>= 1) m = fmaxf(m, __shfl_xor_sync(0xffffffffu, m, o));

    float2 acc = make_float2(0.f, 0.f);
    float dsum = 0.f;
    for (int i = off; i < off + deg; i += 32) {
        int nb = off + deg - i; if (nb > 32) nb = 32;
        int s_l = 0;
        float ex_l = 0.f;
        if (lane < nb) {
            s_l = g_ssrc[i + lane];
            ex_l = __expf(leaky(g_es2[s_l] + edv) - m);
        }
        s_ex[w][lane] = ex_l;
        __syncwarp();
        #pragma unroll 4
        for (int t = 0; t < nb; t++) {
            int s = __shfl_sync(0xffffffffu, s_l, t);
            float ex = s_ex[w][t];
            const float2 z = *(const float2*)&g_z2[s * 64 + 2 * lane];
            dsum += ex;
            acc.x += ex * z.x;
            acc.y += ex * z.y;
        }
        __syncwarp();
    }
    float inv = (deg > 0) ? (1.0f / dsum) : 0.f;
    float2 o;
    o.x = acc.x * inv;
    o.y = acc.y * inv;
    *(float2*)&out[n * 64 + 2 * lane] = o;
}

// ---------------- launch -----------------------------------------------------
extern "C" void kernel_launch(void* const* d_in, const int* in_sizes, int n_in,
                              void* d_out, int out_size) {
    const float* h   = (const float*)d_in[0];
    const int*   src = (const int*)  d_in[1];
    const int*   dst = (const int*)  d_in[2];
    const float* W1  = (const float*)d_in[3];
    const float* a1  = (const float*)d_in[4];
    const float* W2  = (const float*)d_in[5];
    const float* a2  = (const float*)d_in[6];
    float* out = (float*)d_out;

    const int SMEM1 = (256 * 128 + 64 * 256) * 4;   // 196608
    const int SMEM2 = (128 * 64 + 64 * 128) * 4;    //  65536
    cudaFuncSetAttribute(k_gemm1, cudaFuncAttributeMaxDynamicSharedMemorySize, SMEM1);
    cudaFuncSetAttribute(k_gemm2, cudaFuncAttributeMaxDynamicSharedMemorySize, SMEM2);

    // Fork: CSR build (depends only on src/dst) runs concurrently with gemm1
    // (depends only on h/W1/a1). Standard capture-safe event fork/join.
    // Handles are intentionally not destroyed (kernel_launch is called only a
    // handful of times; graph replays do not re-enter this function).
    cudaStream_t side;
    cudaEvent_t evF, evJ;
    cudaStreamCreateWithFlags(&side, cudaStreamNonBlocking);
    cudaEventCreateWithFlags(&evF, cudaEventDisableTiming);
    cudaEventCreateWithFlags(&evJ, cudaEventDisableTiming);

    cudaEventRecord(evF, 0);
    cudaStreamWaitEvent(side, evF, 0);

    // side stream: CSR build (dst shared by both layers)
    k_zero   <<<(N_NODES + 255) / 256, 256, 0, side>>>();
    k_hist   <<<(N_EDGES + 255) / 256, 256, 0, side>>>(dst);
    k_scan   <<<1, 1024, 0, side>>>();
    k_scatter<<<(N_EDGES + 255) / 256, 256, 0, side>>>(src, dst);
    cudaEventRecord(evJ, side);

    // main stream: layer-1 GEMM + attention coeffs (independent of CSR)
    k_gemm1<<<148, 256, SMEM1>>>(h, W1, a1);

    // join: agg1 needs both CSR and gemm1 outputs
    cudaStreamWaitEvent(0, evJ, 0);
    k_agg1 <<<(N_NODES + 7) / 8, 256>>>();

    // layer 2
    k_gemm2<<<296, 256, SMEM2>>>(W2, a2);
    k_agg2 <<<(N_NODES + 7) / 8, 256>>>(out);
}

// round 15
// speedup vs baseline: 1.6715x; 1.0549x over previous
#include <cuda_runtime.h>
#include <math.h>

#define N_NODES 50000
#define N_EDGES 800000
#define IN_DIM  256
#define C1      128     // HEADS * 32
#define HEADS   4
#define HID1    32
#define OUT_DIM 64

typedef unsigned long long u64;

// ---------------- scratch (device globals; no allocation allowed) ------------
__device__ __align__(16) float g_z1 [N_NODES * C1];
__device__ __align__(16) float g_es1[N_NODES * HEADS];
__device__ __align__(16) float g_ed1[N_NODES * HEADS];
__device__ __align__(16) float g_h1 [N_NODES * C1];
__device__ __align__(16) float g_z2 [N_NODES * OUT_DIM];
__device__ float g_es2[N_NODES];
__device__ float g_ed2[N_NODES];
__device__ int   g_deg[N_NODES];
__device__ int   g_pos[N_NODES];
__device__ int   g_off[N_NODES + 1];
__device__ int   g_ssrc[N_EDGES];

__device__ __forceinline__ float leaky(float x) { return x > 0.f ? x : 0.01f * x; }
__device__ __forceinline__ float elu_f(float x) { return x > 0.f ? x : (__expf(x) - 1.f); }

// packed fp32x2 FMA (sm_100+): d = a*b + c elementwise on 2 packed floats
__device__ __forceinline__ u64 ffma2(u64 a, u64 b, u64 c) {
    u64 d;
    asm("fma.rn.f32x2 %0, %1, %2, %3;" : "=l"(d) : "l"(a), "l"(b), "l"(c));
    return d;
}
// duplicate one fp32 into both lanes of a packed f32x2
__device__ __forceinline__ u64 dup2(float x) {
    u64 d; unsigned b = __float_as_uint(x);
    asm("mov.b64 %0, {%1, %1};" : "=l"(d) : "r"(b));
    return d;
}
__device__ __forceinline__ float f2lo(u64 v) { return __uint_as_float((unsigned)v); }
__device__ __forceinline__ float f2hi(u64 v) { return __uint_as_float((unsigned)(v >> 32)); }

// ---------------- CSR build --------------------------------------------------
__global__ void k_zero() {
    int i = blockIdx.x * blockDim.x + threadIdx.x;
    if (i < N_NODES) { g_deg[i] = 0; g_pos[i] = 0; }
}

__global__ void k_hist(const int* __restrict__ dst) {
    int e = blockIdx.x * blockDim.x + threadIdx.x;
    if (e < N_EDGES) atomicAdd(&g_deg[dst[e]], 1);
}

__global__ void k_scan() {
    __shared__ int sm[1024];
    int tid = threadIdx.x;
    const int CH = (N_NODES + 1023) / 1024;   // 49
    int base = tid * CH;
    int s = 0;
    for (int i = 0; i < CH; i++) {
        int idx = base + i;
        if (idx < N_NODES) s += g_deg[idx];
    }
    sm[tid] = s;
    __syncthreads();
    for (int d = 1; d < 1024; d <<= 1) {
        int v = (tid >= d) ? sm[tid - d] : 0;
        __syncthreads();
        sm[tid] += v;
        __syncthreads();
    }
    int run = sm[tid] - s;   // exclusive prefix
    for (int i = 0; i < CH; i++) {
        int idx = base + i;
        if (idx < N_NODES) { g_off[idx] = run; run += g_deg[idx]; }
    }
    if (tid == 1023) g_off[N_NODES] = sm[1023];
}

__global__ void k_scatter(const int* __restrict__ src, const int* __restrict__ dst) {
    int e = blockIdx.x * blockDim.x + threadIdx.x;
    if (e < N_EDGES) {
        int d = dst[e];
        int p = g_off[d] + atomicAdd(&g_pos[d], 1);
        g_ssrc[p] = src[e];
    }
}

// ---------------- layer-1 GEMM + attention coeffs (fused) --------------------
__global__ void __launch_bounds__(256, 1) k_gemm1(const float* __restrict__ x,
                                                  const float* __restrict__ W1,
                                                  const float* __restrict__ a1) {
    extern __shared__ float sm[];
    float* sW = sm;                  // 256*128 floats
    float* sx = sm + 256 * 128;      // 64*256 floats
    int tid = threadIdx.x;           // 256 threads

    // W1 [h][k][d] -> sW[k][h*32+d]
    for (int i = tid; i < HEADS * IN_DIM * HID1; i += 256) {
        int hh = i >> 13, k = (i >> 5) & 255, d = i & 31;
        sW[k * 128 + hh * 32 + d] = W1[i];
    }

    int lane = tid & 31;
    int c0 = lane * 4;                // lane-varying col group (conflict-free)
    int nr = (tid >> 5) * 8;          // warp-uniform node group (broadcast)
    int hl = lane >> 3;               // head owned by this lane
    int d0 = c0 & 31;                 // offset within head
    const float4 as4 = *(const float4*)&a1[hl * 64 + d0];
    const float4 ad4 = *(const float4*)&a1[hl * 64 + 32 + d0];
    int ntiles = (N_NODES + 63) >> 6;

    for (int tile = blockIdx.x; tile < ntiles; tile += gridDim.x) {
        int n0 = tile << 6;
        __syncthreads();
        for (int i = tid; i < 64 * 64; i += 256) {
            int n = n0 + (i >> 6);
            float4 v = make_float4(0.f, 0.f, 0.f, 0.f);
            if (n < N_NODES) v = ((const float4*)x)[n * 64 + (i & 63)];
            ((float4*)sx)[i] = v;
        }
        __syncthreads();

        u64 acc[8][2];
        #pragma unroll
        for (int j = 0; j < 8; j++) { acc[j][0] = 0ull; acc[j][1] = 0ull; }

        const float* xs = sx + nr * 256;
        #pragma unroll 2
        for (int k = 0; k < 256; k += 4) {
            ulonglong2 wp[4];
            #pragma unroll
            for (int kk = 0; kk < 4; kk++)
                wp[kk] = *(const ulonglong2*)&sW[(k + kk) * 128 + c0];
            #pragma unroll
            for (int j = 0; j < 8; j++) {
                float4 xv = *(const float4*)&xs[j * 256 + k];
                u64 x0 = dup2(xv.x), x1 = dup2(xv.y);
                u64 x2 = dup2(xv.z), x3 = dup2(xv.w);
                acc[j][0] = ffma2(x0, wp[0].x, acc[j][0]);
                acc[j][1] = ffma2(x0, wp[0].y, acc[j][1]);
                acc[j][0] = ffma2(x1, wp[1].x, acc[j][0]);
                acc[j][1] = ffma2(x1, wp[1].y, acc[j][1]);
                acc[j][0] = ffma2(x2, wp[2].x, acc[j][0]);
                acc[j][1] = ffma2(x2, wp[2].y, acc[j][1]);
                acc[j][0] = ffma2(x3, wp[3].x, acc[j][0]);
                acc[j][1] = ffma2(x3, wp[3].y, acc[j][1]);
            }
        }

        #pragma unroll
        for (int j = 0; j < 8; j++) {
            int n = n0 + nr + j;          // warp-uniform
            float4 o;
            o.x = f2lo(acc[j][0]); o.y = f2hi(acc[j][0]);
            o.z = f2lo(acc[j][1]); o.w = f2hi(acc[j][1]);
            float es = o.x * as4.x + o.y * as4.y + o.z * as4.z + o.w * as4.w;
            float ed = o.x * ad4.x + o.y * ad4.y + o.z * ad4.z + o.w * ad4.w;
            #pragma unroll
            for (int m = 4; m; m >>= 1) {
                es += __shfl_xor_sync(0xffffffffu, es, m);
                ed += __shfl_xor_sync(0xffffffffu, ed, m);
            }
            if (n < N_NODES) {
                ulonglong2 ov; ov.x = acc[j][0]; ov.y = acc[j][1];
                *(ulonglong2*)&g_z1[n * 128 + c0] = ov;
                if ((lane & 7) == 0) {
                    g_es1[n * 4 + hl] = es;
                    g_ed1[n * 4 + hl] = ed;
                }
            }
        }
    }
}

// ---------------- layer-1 aggregation: half-warp per node, no max pass -------
// lanes 0-15 -> node 2w, lanes 16-31 -> node 2w+1; each lane owns 8 channels.
__global__ void __launch_bounds__(256) k_agg1() {
    __shared__ float s_ex[8][2][64];   // [warp][half][16 edges * 4 heads]
    __shared__ int   s_si[8][2][16];
    int gwarp = (blockIdx.x * blockDim.x + threadIdx.x) >> 5;
    int lane  = threadIdx.x & 31;
    int w     = threadIdx.x >> 5;
    int hw    = lane >> 4;
    int hlane = lane & 15;
    int n = gwarp * 2 + hw;
    bool active = (n < N_NODES);

    int off = 0, deg = 0;
    float4 ed4 = make_float4(0.f, 0.f, 0.f, 0.f);
    if (active) {
        off = g_off[n];
        deg = g_off[n + 1] - off;
        ed4 = *(const float4*)&g_ed1[n * 4];
    }

    int nblk_l = (deg + 15) >> 4;
    int nblk = max(nblk_l, __shfl_xor_sync(0xffffffffu, nblk_l, 16));

    int hl = hlane >> 2;           // head of this lane's 8 channels
    int cc = hlane * 8;            // channel base

    float4 accA = make_float4(0.f, 0.f, 0.f, 0.f);
    float4 accB = make_float4(0.f, 0.f, 0.f, 0.f);
    float dsum = 0.f;

    for (int b = 0; b < nblk; b++) {
        int i  = off + (b << 4);
        int nb = min(deg - (b << 4), 16); if (nb < 0) nb = 0;
        int s_l = 0;
        float4 ex4 = make_float4(0.f, 0.f, 0.f, 0.f);
        if (hlane < nb) {
            s_l = g_ssrc[i + hlane];
            float4 es4 = *(const float4*)&g_es1[s_l * 4];
            ex4.x = __expf(leaky(es4.x + ed4.x));
            ex4.y = __expf(leaky(es4.y + ed4.y));
            ex4.z = __expf(leaky(es4.z + ed4.z));
            ex4.w = __expf(leaky(es4.w + ed4.w));
        }
        __syncwarp();              // prior block's smem reads done
        s_si[w][hw][hlane] = s_l;
        *(float4*)&s_ex[w][hw][hlane * 4] = ex4;
        __syncwarp();
        for (int t = 0; t < nb; t++) {    // divergent between halves: no syncs inside
            int s = s_si[w][hw][t];
            float ex = s_ex[w][hw][t * 4 + hl];
            float4 za = *(const float4*)&g_z1[s * 128 + cc];
            float4 zb = *(const float4*)&g_z1[s * 128 + cc + 4];
            dsum += ex;
            accA.x += ex * za.x; accA.y += ex * za.y;
            accA.z += ex * za.z; accA.w += ex * za.w;
            accB.x += ex * zb.x; accB.y += ex * zb.y;
            accB.z += ex * zb.z; accB.w += ex * zb.w;
        }
    }

    if (active) {
        float inv = (deg > 0) ? (1.0f / dsum) : 0.f;
        float4 oA, oB;
        oA.x = elu_f(accA.x * inv); oA.y = elu_f(accA.y * inv);
        oA.z = elu_f(accA.z * inv); oA.w = elu_f(accA.w * inv);
        oB.x = elu_f(accB.x * inv); oB.y = elu_f(accB.y * inv);
        oB.z = elu_f(accB.z * inv); oB.w = elu_f(accB.w * inv);
        *(float4*)&g_h1[n * 128 + cc]     = oA;
        *(float4*)&g_h1[n * 128 + cc + 4] = oB;
    }
}

// ---------------- layer-2 GEMM + attention coeffs (fused) --------------------
__global__ void __launch_bounds__(256) k_gemm2(const float* __restrict__ W2,
                                               const float* __restrict__ a2) {
    extern __shared__ float sm[];
    float* sW = sm;                 // 128*64 floats
    float* sx = sm + 128 * 64;      // 64*128 floats
    int tid = threadIdx.x;          // 256 threads

    for (int i = tid; i < 128 * 64; i += 256) sW[i] = W2[i];

    int lane = tid & 31;
    int c0 = (tid & 15) * 4;        // 16 col-groups of 4
    int nr = (tid >> 4) * 4;        // 16 node-groups of 4 (uniform per half-warp)
    const float4 as4 = *(const float4*)&a2[c0];
    const float4 ad4 = *(const float4*)&a2[64 + c0];
    int ntiles = (N_NODES + 63) >> 6;

    for (int tile = blockIdx.x; tile < ntiles; tile += gridDim.x) {
        int n0 = tile << 6;
        __syncthreads();
        for (int i = tid; i < 64 * 32; i += 256) {
            int n = n0 + (i >> 5);
            float4 v = make_float4(0.f, 0.f, 0.f, 0.f);
            if (n < N_NODES) v = ((const float4*)g_h1)[n * 32 + (i & 31)];
            ((float4*)sx)[i] = v;
        }
        __syncthreads();

        u64 acc[4][2];
        #pragma unroll
        for (int j = 0; j < 4; j++) { acc[j][0] = 0ull; acc[j][1] = 0ull; }

        const float* xs = sx + nr * 128;
        #pragma unroll 2
        for (int k = 0; k < 128; k += 4) {
            ulonglong2 wp[4];
            #pragma unroll
            for (int kk = 0; kk < 4; kk++)
                wp[kk] = *(const ulonglong2*)&sW[(k + kk) * 64 + c0];
            #pragma unroll
            for (int j = 0; j < 4; j++) {
                float4 xv = *(const float4*)&xs[j * 128 + k];
                u64 x0 = dup2(xv.x), x1 = dup2(xv.y);
                u64 x2 = dup2(xv.z), x3 = dup2(xv.w);
                acc[j][0] = ffma2(x0, wp[0].x, acc[j][0]);
                acc[j][1] = ffma2(x0, wp[0].y, acc[j][1]);
                acc[j][0] = ffma2(x1, wp[1].x, acc[j][0]);
                acc[j][1] = ffma2(x1, wp[1].y, acc[j][1]);
                acc[j][0] = ffma2(x2, wp[2].x, acc[j][0]);
                acc[j][1] = ffma2(x2, wp[2].y, acc[j][1]);
                acc[j][0] = ffma2(x3, wp[3].x, acc[j][0]);
                acc[j][1] = ffma2(x3, wp[3].y, acc[j][1]);
            }
        }

        #pragma unroll
        for (int j = 0; j < 4; j++) {
            int n = n0 + nr + j;      // uniform per half-warp
            float4 o;
            o.x = f2lo(acc[j][0]); o.y = f2hi(acc[j][0]);
            o.z = f2lo(acc[j][1]); o.w = f2hi(acc[j][1]);
            float es = o.x * as4.x + o.y * as4.y + o.z * as4.z + o.w * as4.w;
            float ed = o.x * ad4.x + o.y * ad4.y + o.z * ad4.z + o.w * ad4.w;
            #pragma unroll
            for (int m = 8; m; m >>= 1) {
                es += __shfl_xor_sync(0xffffffffu, es, m);
                ed += __shfl_xor_sync(0xffffffffu, ed, m);
            }
            if (n < N_NODES) {
                ulonglong2 ov; ov.x = acc[j][0]; ov.y = acc[j][1];
                *(ulonglong2*)&g_z2[n * 64 + c0] = ov;
                if ((lane & 15) == 0) {
                    g_es2[n] = es;
                    g_ed2[n] = ed;
                }
            }
        }
    }
}

// ---------------- layer-2 aggregation: half-warp per node, no max pass -------
// each lane owns 4 channels (hlane*4); ex scalar per edge.
__global__ void __launch_bounds__(256) k_agg2(float* __restrict__ out) {
    __shared__ float s_ex[8][2][16];
    __shared__ int   s_si[8][2][16];
    int gwarp = (blockIdx.x * blockDim.x + threadIdx.x) >> 5;
    int lane  = threadIdx.x & 31;
    int w     = threadIdx.x >> 5;
    int hw    = lane >> 4;
    int hlane = lane & 15;
    int n = gwarp * 2 + hw;
    bool active = (n < N_NODES);

    int off = 0, deg = 0;
    float edv = 0.f;
    if (active) {
        off = g_off[n];
        deg = g_off[n + 1] - off;
        edv = g_ed2[n];
    }

    int nblk_l = (deg + 15) >> 4;
    int nblk = max(nblk_l, __shfl_xor_sync(0xffffffffu, nblk_l, 16));

    int cc = hlane * 4;

    float4 acc = make_float4(0.f, 0.f, 0.f, 0.f);
    float dsum = 0.f;

    for (int b = 0; b < nblk; b++) {
        int i  = off + (b << 4);
        int nb = min(deg - (b << 4), 16); if (nb < 0) nb = 0;
        int s_l = 0;
        float ex_l = 0.f;
        if (hlane < nb) {
            s_l = g_ssrc[i + hlane];
            ex_l = __expf(leaky(g_es2[s_l] + edv));
        }
        __syncwarp();
        s_si[w][hw][hlane] = s_l;
        s_ex[w][hw][hlane] = ex_l;
        __syncwarp();
        for (int t = 0; t < nb; t++) {
            int s = s_si[w][hw][t];
            float ex = s_ex[w][hw][t];
            float4 z = *(const float4*)&g_z2[s * 64 + cc];
            dsum += ex;
            acc.x += ex * z.x; acc.y += ex * z.y;
            acc.z += ex * z.z; acc.w += ex * z.w;
        }
    }

    if (active) {
        float inv = (deg > 0) ? (1.0f / dsum) : 0.f;
        float4 o;
        o.x = acc.x * inv; o.y = acc.y * inv;
        o.z = acc.z * inv; o.w = acc.w * inv;
        *(float4*)&out[n * 64 + cc] = o;
    }
}

// ---------------- launch -----------------------------------------------------
extern "C" void kernel_launch(void* const* d_in, const int* in_sizes, int n_in,
                              void* d_out, int out_size) {
    const float* h   = (const float*)d_in[0];
    const int*   src = (const int*)  d_in[1];
    const int*   dst = (const int*)  d_in[2];
    const float* W1  = (const float*)d_in[3];
    const float* a1  = (const float*)d_in[4];
    const float* W2  = (const float*)d_in[5];
    const float* a2  = (const float*)d_in[6];
    float* out = (float*)d_out;

    const int SMEM1 = (256 * 128 + 64 * 256) * 4;   // 196608
    const int SMEM2 = (128 * 64 + 64 * 128) * 4;    //  65536
    cudaFuncSetAttribute(k_gemm1, cudaFuncAttributeMaxDynamicSharedMemorySize, SMEM1);
    cudaFuncSetAttribute(k_gemm2, cudaFuncAttributeMaxDynamicSharedMemorySize, SMEM2);

    // Fork: CSR build (depends only on src/dst) runs concurrently with gemm1
    // (depends only on h/W1/a1). Capture-safe event fork/join.
    cudaStream_t side;
    cudaEvent_t evF, evJ;
    cudaStreamCreateWithFlags(&side, cudaStreamNonBlocking);
    cudaEventCreateWithFlags(&evF, cudaEventDisableTiming);
    cudaEventCreateWithFlags(&evJ, cudaEventDisableTiming);

    cudaEventRecord(evF, 0);
    cudaStreamWaitEvent(side, evF, 0);

    // side stream: CSR build (dst shared by both layers)
    k_zero   <<<(N_NODES + 255) / 256, 256, 0, side>>>();
    k_hist   <<<(N_EDGES + 255) / 256, 256, 0, side>>>(dst);
    k_scan   <<<1, 1024, 0, side>>>();
    k_scatter<<<(N_EDGES + 255) / 256, 256, 0, side>>>(src, dst);
    cudaEventRecord(evJ, side);

    // main stream: layer-1 GEMM + attention coeffs (independent of CSR)
    k_gemm1<<<148, 256, SMEM1>>>(h, W1, a1);

    // join: agg1 needs both CSR and gemm1 outputs
    cudaStreamWaitEvent(0, evJ, 0);
    k_agg1 <<<(N_NODES + 15) / 16, 256>>>();      // half-warp per node

    // layer 2
    k_gemm2<<<296, 256, SMEM2>>>(W2, a2);
    k_agg2 <<<(N_NODES + 15) / 16, 256>>>(out);   // half-warp per node
}

// round 16
// speedup vs baseline: 1.6821x; 1.0063x over previous
#include <cuda_runtime.h>
#include <math.h>

#define N_NODES 50000
#define N_EDGES 800000
#define IN_DIM  256
#define C1      128     // HEADS * 32
#define HEADS   4
#define HID1    32
#define OUT_DIM 64

typedef unsigned long long u64;

// ---------------- scratch (device globals; no allocation allowed) ------------
__device__ __align__(16) float g_z1 [N_NODES * C1];
__device__ __align__(16) float g_es1[N_NODES * HEADS];
__device__ __align__(16) float g_ed1[N_NODES * HEADS];
__device__ __align__(16) float g_h1 [N_NODES * C1];
__device__ __align__(16) float g_z2 [N_NODES * OUT_DIM];
__device__ float g_es2[N_NODES];
__device__ float g_ed2[N_NODES];
__device__ int   g_deg[N_NODES];
__device__ int   g_pos[N_NODES];
__device__ int   g_off[N_NODES + 1];
__device__ int   g_ssrc[N_EDGES];

__device__ __forceinline__ float leaky(float x) { return x > 0.f ? x : 0.01f * x; }
__device__ __forceinline__ float elu_f(float x) { return x > 0.f ? x : (__expf(x) - 1.f); }

// packed fp32x2 FMA (sm_100+): d = a*b + c elementwise on 2 packed floats
__device__ __forceinline__ u64 ffma2(u64 a, u64 b, u64 c) {
    u64 d;
    asm("fma.rn.f32x2 %0, %1, %2, %3;" : "=l"(d) : "l"(a), "l"(b), "l"(c));
    return d;
}
// duplicate one fp32 into both lanes of a packed f32x2
__device__ __forceinline__ u64 dup2(float x) {
    u64 d; unsigned b = __float_as_uint(x);
    asm("mov.b64 %0, {%1, %1};" : "=l"(d) : "r"(b));
    return d;
}
__device__ __forceinline__ float f2lo(u64 v) { return __uint_as_float((unsigned)v); }
__device__ __forceinline__ float f2hi(u64 v) { return __uint_as_float((unsigned)(v >> 32)); }

// ---------------- CSR build --------------------------------------------------
__global__ void k_zero() {
    int i = blockIdx.x * blockDim.x + threadIdx.x;
    if (i < N_NODES) { g_deg[i] = 0; g_pos[i] = 0; }
}

__global__ void k_hist(const int* __restrict__ dst) {
    int e = blockIdx.x * blockDim.x + threadIdx.x;
    if (e < N_EDGES) atomicAdd(&g_deg[dst[e]], 1);
}

__global__ void k_scan() {
    __shared__ int sm[1024];
    int tid = threadIdx.x;
    const int CH = (N_NODES + 1023) / 1024;   // 49
    int base = tid * CH;
    int s = 0;
    for (int i = 0; i < CH; i++) {
        int idx = base + i;
        if (idx < N_NODES) s += g_deg[idx];
    }
    sm[tid] = s;
    __syncthreads();
    for (int d = 1; d < 1024; d <<= 1) {
        int v = (tid >= d) ? sm[tid - d] : 0;
        __syncthreads();
        sm[tid] += v;
        __syncthreads();
    }
    int run = sm[tid] - s;   // exclusive prefix
    for (int i = 0; i < CH; i++) {
        int idx = base + i;
        if (idx < N_NODES) { g_off[idx] = run; run += g_deg[idx]; }
    }
    if (tid == 1023) g_off[N_NODES] = sm[1023];
}

__global__ void k_scatter(const int* __restrict__ src, const int* __restrict__ dst) {
    int e = blockIdx.x * blockDim.x + threadIdx.x;
    if (e < N_EDGES) {
        int d = dst[e];
        int p = g_off[d] + atomicAdd(&g_pos[d], 1);
        g_ssrc[p] = src[e];
    }
}

// ---------------- layer-1 GEMM + attention coeffs (fused) --------------------
__global__ void __launch_bounds__(256, 1) k_gemm1(const float* __restrict__ x,
                                                  const float* __restrict__ W1,
                                                  const float* __restrict__ a1) {
    extern __shared__ float sm[];
    float* sW = sm;                  // 256*128 floats
    float* sx = sm + 256 * 128;      // 64*256 floats
    int tid = threadIdx.x;           // 256 threads

    // W1 [h][k][d] -> sW[k][h*32+d]
    for (int i = tid; i < HEADS * IN_DIM * HID1; i += 256) {
        int hh = i >> 13, k = (i >> 5) & 255, d = i & 31;
        sW[k * 128 + hh * 32 + d] = W1[i];
    }

    int lane = tid & 31;
    int c0 = lane * 4;                // lane-varying col group (conflict-free)
    int nr = (tid >> 5) * 8;          // warp-uniform node group (broadcast)
    int hl = lane >> 3;               // head owned by this lane
    int d0 = c0 & 31;                 // offset within head
    const float4 as4 = *(const float4*)&a1[hl * 64 + d0];
    const float4 ad4 = *(const float4*)&a1[hl * 64 + 32 + d0];
    int ntiles = (N_NODES + 63) >> 6;

    for (int tile = blockIdx.x; tile < ntiles; tile += gridDim.x) {
        int n0 = tile << 6;
        __syncthreads();
        for (int i = tid; i < 64 * 64; i += 256) {
            int n = n0 + (i >> 6);
            float4 v = make_float4(0.f, 0.f, 0.f, 0.f);
            if (n < N_NODES) v = ((const float4*)x)[n * 64 + (i & 63)];
            ((float4*)sx)[i] = v;
        }
        __syncthreads();

        u64 acc[8][2];
        #pragma unroll
        for (int j = 0; j < 8; j++) { acc[j][0] = 0ull; acc[j][1] = 0ull; }

        const float* xs = sx + nr * 256;
        #pragma unroll 2
        for (int k = 0; k < 256; k += 4) {
            ulonglong2 wp[4];
            #pragma unroll
            for (int kk = 0; kk < 4; kk++)
                wp[kk] = *(const ulonglong2*)&sW[(k + kk) * 128 + c0];
            #pragma unroll
            for (int j = 0; j < 8; j++) {
                float4 xv = *(const float4*)&xs[j * 256 + k];
                u64 x0 = dup2(xv.x), x1 = dup2(xv.y);
                u64 x2 = dup2(xv.z), x3 = dup2(xv.w);
                acc[j][0] = ffma2(x0, wp[0].x, acc[j][0]);
                acc[j][1] = ffma2(x0, wp[0].y, acc[j][1]);
                acc[j][0] = ffma2(x1, wp[1].x, acc[j][0]);
                acc[j][1] = ffma2(x1, wp[1].y, acc[j][1]);
                acc[j][0] = ffma2(x2, wp[2].x, acc[j][0]);
                acc[j][1] = ffma2(x2, wp[2].y, acc[j][1]);
                acc[j][0] = ffma2(x3, wp[3].x, acc[j][0]);
                acc[j][1] = ffma2(x3, wp[3].y, acc[j][1]);
            }
        }

        #pragma unroll
        for (int j = 0; j < 8; j++) {
            int n = n0 + nr + j;          // warp-uniform
            float4 o;
            o.x = f2lo(acc[j][0]); o.y = f2hi(acc[j][0]);
            o.z = f2lo(acc[j][1]); o.w = f2hi(acc[j][1]);
            float es = o.x * as4.x + o.y * as4.y + o.z * as4.z + o.w * as4.w;
            float ed = o.x * ad4.x + o.y * ad4.y + o.z * ad4.z + o.w * ad4.w;
            #pragma unroll
            for (int m = 4; m; m >>= 1) {
                es += __shfl_xor_sync(0xffffffffu, es, m);
                ed += __shfl_xor_sync(0xffffffffu, ed, m);
            }
            if (n < N_NODES) {
                ulonglong2 ov; ov.x = acc[j][0]; ov.y = acc[j][1];
                *(ulonglong2*)&g_z1[n * 128 + c0] = ov;
                if ((lane & 7) == 0) {
                    g_es1[n * 4 + hl] = es;
                    g_ed1[n * 4 + hl] = ed;
                }
            }
        }
    }
}

// ---------------- layer-1 aggregation: half-warp per node, chunked MLP -------
// lanes 0-15 -> node 2w, lanes 16-31 -> node 2w+1; each lane owns 8 channels.
// Gather loop runs in chunks of 4 edges with all 8 LDG.128 front-batched.
__global__ void __launch_bounds__(256) k_agg1() {
    __shared__ float s_ex[8][2][64];   // [warp][half][16 edges * 4 heads]
    __shared__ int   s_si[8][2][16];
    int gwarp = (blockIdx.x * blockDim.x + threadIdx.x) >> 5;
    int lane  = threadIdx.x & 31;
    int w     = threadIdx.x >> 5;
    int hw    = lane >> 4;
    int hlane = lane & 15;
    int n = gwarp * 2 + hw;
    bool active = (n < N_NODES);

    int off = 0, deg = 0;
    float4 ed4 = make_float4(0.f, 0.f, 0.f, 0.f);
    if (active) {
        off = g_off[n];
        deg = g_off[n + 1] - off;
        ed4 = *(const float4*)&g_ed1[n * 4];
    }

    int nblk_l = (deg + 15) >> 4;
    int nblk = max(nblk_l, __shfl_xor_sync(0xffffffffu, nblk_l, 16));

    int hl = hlane >> 2;           // head of this lane's 8 channels
    int cc = hlane * 8;            // channel base

    float4 accA = make_float4(0.f, 0.f, 0.f, 0.f);
    float4 accB = make_float4(0.f, 0.f, 0.f, 0.f);
    float dsum = 0.f;

    for (int b = 0; b < nblk; b++) {
        int nb = min(deg - (b << 4), 16); if (nb < 0) nb = 0;
        int i  = off + (b << 4);
        int s_l = 0;
        float4 ex4 = make_float4(0.f, 0.f, 0.f, 0.f);
        if (hlane < nb) {
            s_l = g_ssrc[i + hlane];
            float4 es4 = *(const float4*)&g_es1[s_l * 4];
            ex4.x = __expf(leaky(es4.x + ed4.x));
            ex4.y = __expf(leaky(es4.y + ed4.y));
            ex4.z = __expf(leaky(es4.z + ed4.z));
            ex4.w = __expf(leaky(es4.w + ed4.w));
        }
        __syncwarp();              // prior block's smem reads done
        s_si[w][hw][hlane] = s_l;
        *(float4*)&s_ex[w][hw][hlane * 4] = ex4;
        __syncwarp();
        int nbr = (nb + 3) & ~3;   // padded chunks: ex=0 entries contribute 0
        for (int t = 0; t < nbr; t += 4) {
            int   ss[4]; float exv[4]; float4 za[4], zb[4];
            #pragma unroll
            for (int u = 0; u < 4; u++) {
                ss[u]  = s_si[w][hw][t + u];
                exv[u] = s_ex[w][hw][(t + u) * 4 + hl];
            }
            #pragma unroll
            for (int u = 0; u < 4; u++) {
                za[u] = *(const float4*)&g_z1[ss[u] * 128 + cc];
                zb[u] = *(const float4*)&g_z1[ss[u] * 128 + cc + 4];
            }
            #pragma unroll
            for (int u = 0; u < 4; u++) {
                dsum += exv[u];
                accA.x += exv[u] * za[u].x; accA.y += exv[u] * za[u].y;
                accA.z += exv[u] * za[u].z; accA.w += exv[u] * za[u].w;
                accB.x += exv[u] * zb[u].x; accB.y += exv[u] * zb[u].y;
                accB.z += exv[u] * zb[u].z; accB.w += exv[u] * zb[u].w;
            }
        }
    }

    if (active) {
        float inv = (deg > 0) ? (1.0f / dsum) : 0.f;
        float4 oA, oB;
        oA.x = elu_f(accA.x * inv); oA.y = elu_f(accA.y * inv);
        oA.z = elu_f(accA.z * inv); oA.w = elu_f(accA.w * inv);
        oB.x = elu_f(accB.x * inv); oB.y = elu_f(accB.y * inv);
        oB.z = elu_f(accB.z * inv); oB.w = elu_f(accB.w * inv);
        *(float4*)&g_h1[n * 128 + cc]     = oA;
        *(float4*)&g_h1[n * 128 + cc + 4] = oB;
    }
}

// ---------------- layer-2 GEMM + attention coeffs (fused) --------------------
__global__ void __launch_bounds__(256) k_gemm2(const float* __restrict__ W2,
                                               const float* __restrict__ a2) {
    extern __shared__ float sm[];
    float* sW = sm;                 // 128*64 floats
    float* sx = sm + 128 * 64;      // 64*128 floats
    int tid = threadIdx.x;          // 256 threads

    for (int i = tid; i < 128 * 64; i += 256) sW[i] = W2[i];

    int lane = tid & 31;
    int c0 = (tid & 15) * 4;        // 16 col-groups of 4
    int nr = (tid >> 4) * 4;        // 16 node-groups of 4 (uniform per half-warp)
    const float4 as4 = *(const float4*)&a2[c0];
    const float4 ad4 = *(const float4*)&a2[64 + c0];
    int ntiles = (N_NODES + 63) >> 6;

    for (int tile = blockIdx.x; tile < ntiles; tile += gridDim.x) {
        int n0 = tile << 6;
        __syncthreads();
        for (int i = tid; i < 64 * 32; i += 256) {
            int n = n0 + (i >> 5);
            float4 v = make_float4(0.f, 0.f, 0.f, 0.f);
            if (n < N_NODES) v = ((const float4*)g_h1)[n * 32 + (i & 31)];
            ((float4*)sx)[i] = v;
        }
        __syncthreads();

        u64 acc[4][2];
        #pragma unroll
        for (int j = 0; j < 4; j++) { acc[j][0] = 0ull; acc[j][1] = 0ull; }

        const float* xs = sx + nr * 128;
        #pragma unroll 2
        for (int k = 0; k < 128; k += 4) {
            ulonglong2 wp[4];
            #pragma unroll
            for (int kk = 0; kk < 4; kk++)
                wp[kk] = *(const ulonglong2*)&sW[(k + kk) * 64 + c0];
            #pragma unroll
            for (int j = 0; j < 4; j++) {
                float4 xv = *(const float4*)&xs[j * 128 + k];
                u64 x0 = dup2(xv.x), x1 = dup2(xv.y);
                u64 x2 = dup2(xv.z), x3 = dup2(xv.w);
                acc[j][0] = ffma2(x0, wp[0].x, acc[j][0]);
                acc[j][1] = ffma2(x0, wp[0].y, acc[j][1]);
                acc[j][0] = ffma2(x1, wp[1].x, acc[j][0]);
                acc[j][1] = ffma2(x1, wp[1].y, acc[j][1]);
                acc[j][0] = ffma2(x2, wp[2].x, acc[j][0]);
                acc[j][1] = ffma2(x2, wp[2].y, acc[j][1]);
                acc[j][0] = ffma2(x3, wp[3].x, acc[j][0]);
                acc[j][1] = ffma2(x3, wp[3].y, acc[j][1]);
            }
        }

        #pragma unroll
        for (int j = 0; j < 4; j++) {
            int n = n0 + nr + j;      // uniform per half-warp
            float4 o;
            o.x = f2lo(acc[j][0]); o.y = f2hi(acc[j][0]);
            o.z = f2lo(acc[j][1]); o.w = f2hi(acc[j][1]);
            float es = o.x * as4.x + o.y * as4.y + o.z * as4.z + o.w * as4.w;
            float ed = o.x * ad4.x + o.y * ad4.y + o.z * ad4.z + o.w * ad4.w;
            #pragma unroll
            for (int m = 8; m; m >>= 1) {
                es += __shfl_xor_sync(0xffffffffu, es, m);
                ed += __shfl_xor_sync(0xffffffffu, ed, m);
            }
            if (n < N_NODES) {
                ulonglong2 ov; ov.x = acc[j][0]; ov.y = acc[j][1];
                *(ulonglong2*)&g_z2[n * 64 + c0] = ov;
                if ((lane & 15) == 0) {
                    g_es2[n] = es;
                    g_ed2[n] = ed;
                }
            }
        }
    }
}

// ---------------- layer-2 aggregation: half-warp per node, chunked MLP -------
// each lane owns 4 channels (hlane*4); chunks of 8 edges, loads front-batched.
__global__ void __launch_bounds__(256) k_agg2(float* __restrict__ out) {
    __shared__ float s_ex[8][2][16];
    __shared__ int   s_si[8][2][16];
    int gwarp = (blockIdx.x * blockDim.x + threadIdx.x) >> 5;
    int lane  = threadIdx.x & 31;
    int w     = threadIdx.x >> 5;
    int hw    = lane >> 4;
    int hlane = lane & 15;
    int n = gwarp * 2 + hw;
    bool active = (n < N_NODES);

    int off = 0, deg = 0;
    float edv = 0.f;
    if (active) {
        off = g_off[n];
        deg = g_off[n + 1] - off;
        edv = g_ed2[n];
    }

    int nblk_l = (deg + 15) >> 4;
    int nblk = max(nblk_l, __shfl_xor_sync(0xffffffffu, nblk_l, 16));

    int cc = hlane * 4;

    float4 acc = make_float4(0.f, 0.f, 0.f, 0.f);
    float dsum = 0.f;

    for (int b = 0; b < nblk; b++) {
        int nb = min(deg - (b << 4), 16); if (nb < 0) nb = 0;
        int i  = off + (b << 4);
        int s_l = 0;
        float ex_l = 0.f;
        if (hlane < nb) {
            s_l = g_ssrc[i + hlane];
            ex_l = __expf(leaky(g_es2[s_l] + edv));
        }
        __syncwarp();
        s_si[w][hw][hlane] = s_l;
        s_ex[w][hw][hlane] = ex_l;
        __syncwarp();
        int nbr = (nb + 7) & ~7;   // padded chunks: ex=0 entries contribute 0
        for (int t = 0; t < nbr; t += 8) {
            int ss[8]; float exv[8]; float4 zv[8];
            #pragma unroll
            for (int u = 0; u < 8; u++) {
                ss[u]  = s_si[w][hw][t + u];
                exv[u] = s_ex[w][hw][t + u];
            }
            #pragma unroll
            for (int u = 0; u < 8; u++)
                zv[u] = *(const float4*)&g_z2[ss[u] * 64 + cc];
            #pragma unroll
            for (int u = 0; u < 8; u++) {
                dsum += exv[u];
                acc.x += exv[u] * zv[u].x; acc.y += exv[u] * zv[u].y;
                acc.z += exv[u] * zv[u].z; acc.w += exv[u] * zv[u].w;
            }
        }
    }

    if (active) {
        float inv = (deg > 0) ? (1.0f / dsum) : 0.f;
        float4 o;
        o.x = acc.x * inv; o.y = acc.y * inv;
        o.z = acc.z * inv; o.w = acc.w * inv;
        *(float4*)&out[n * 64 + cc] = o;
    }
}

// ---------------- launch -----------------------------------------------------
extern "C" void kernel_launch(void* const* d_in, const int* in_sizes, int n_in,
                              void* d_out, int out_size) {
    const float* h   = (const float*)d_in[0];
    const int*   src = (const int*)  d_in[1];
    const int*   dst = (const int*)  d_in[2];
    const float* W1  = (const float*)d_in[3];
    const float* a1  = (const float*)d_in[4];
    const float* W2  = (const float*)d_in[5];
    const float* a2  = (const float*)d_in[6];
    float* out = (float*)d_out;

    const int SMEM1 = (256 * 128 + 64 * 256) * 4;   // 196608
    const int SMEM2 = (128 * 64 + 64 * 128) * 4;    //  65536
    cudaFuncSetAttribute(k_gemm1, cudaFuncAttributeMaxDynamicSharedMemorySize, SMEM1);
    cudaFuncSetAttribute(k_gemm2, cudaFuncAttributeMaxDynamicSharedMemorySize, SMEM2);

    // Fork: CSR build (depends only on src/dst) runs concurrently with gemm1
    // (depends only on h/W1/a1). Capture-safe event fork/join.
    cudaStream_t side;
    cudaEvent_t evF, evJ;
    cudaStreamCreateWithFlags(&side, cudaStreamNonBlocking);
    cudaEventCreateWithFlags(&evF, cudaEventDisableTiming);
    cudaEventCreateWithFlags(&evJ, cudaEventDisableTiming);

    cudaEventRecord(evF, 0);
    cudaStreamWaitEvent(side, evF, 0);

    // side stream: CSR build (dst shared by both layers)
    k_zero   <<<(N_NODES + 255) / 256, 256, 0, side>>>();
    k_hist   <<<(N_EDGES + 255) / 256, 256, 0, side>>>(dst);
    k_scan   <<<1, 1024, 0, side>>>();
    k_scatter<<<(N_EDGES + 255) / 256, 256, 0, side>>>(src, dst);
    cudaEventRecord(evJ, side);

    // main stream: layer-1 GEMM + attention coeffs (independent of CSR)
    k_gemm1<<<148, 256, SMEM1>>>(h, W1, a1);

    // join: agg1 needs both CSR and gemm1 outputs
    cudaStreamWaitEvent(0, evJ, 0);
    k_agg1 <<<(N_NODES + 15) / 16, 256>>>();      // half-warp per node

    // layer 2
    k_gemm2<<<296, 256, SMEM2>>>(W2, a2);
    k_agg2 <<<(N_NODES + 15) / 16, 256>>>(out);   // half-warp per node
}